// round 5
// baseline (speedup 1.0000x reference)
#include <cuda_runtime.h>
#include <cstdint>

#define N_MAX 100000
#define E_MAX 1250000

// ---------------- scratch (static device allocations; no runtime alloc) -----
__device__ int   g_is64;
__device__ int   g_deg[N_MAX];
__device__ int   g_incl[N_MAX];
__device__ int   g_rowptr[N_MAX];
__device__ int   g_cursor[N_MAX];
__device__ int   g_bsum[256];
__device__ float g_dinv[N_MAX];   // rsqrt(indeg+1)  (GCN)
__device__ float g_cinv[N_MAX];   // 1/max(indeg,1)  (SAGE mean)
__device__ int2  g_edge[E_MAX];   // (src, gcn_edge_weight_as_int) bucketed by dst
__device__ float g_buf[6][(size_t)N_MAX * 64];

// ---------------- edge-index dtype detection (int64 vs int32) ---------------
__global__ void k_detect(const void* __restrict__ ei, int e, int n) {
    __shared__ int bad;
    if (threadIdx.x == 0) bad = 0;
    __syncthreads();
    const long long* p = (const long long*)ei;
    int m = e < 2048 ? e : 2048;   // first m int64 reads stay within even an int32 buffer
    for (int i = threadIdx.x; i < m; i += blockDim.x) {
        long long v = p[i];
        if (v < 0 || v >= (long long)n) bad = 1;
    }
    __syncthreads();
    if (threadIdx.x == 0) g_is64 = bad ? 0 : 1;
}

__device__ __forceinline__ int ld_idx(const void* __restrict__ ei, int is64,
                                      long long pos, int n) {
    long long v = is64 ? ((const long long*)ei)[pos]
                       : (long long)((const int*)ei)[pos];
    int s = (int)v;
    if ((unsigned)s >= (unsigned)n) s = 0;   // trap-safety clamp (no-op when data is sane)
    return s;
}

// ---------------- CSR build --------------------------------------------------
__global__ void k_zero_deg(int n) {
    int i = blockIdx.x * blockDim.x + threadIdx.x;
    if (i < n) g_deg[i] = 0;
}

__global__ void k_count(const void* __restrict__ ei, int e, int n) {
    int i = blockIdx.x * blockDim.x + threadIdx.x;
    if (i >= e) return;
    int is64 = g_is64;
    int d = ld_idx(ei, is64, (long long)e + i, n);
    atomicAdd(&g_deg[d], 1);
}

__global__ void k_scan1(int n) {  // per-block inclusive scan of g_deg (1024/block)
    __shared__ int sh[1024];
    int t = threadIdx.x;
    int i = blockIdx.x * 1024 + t;
    int v = (i < n) ? g_deg[i] : 0;
    sh[t] = v;
    __syncthreads();
    for (int off = 1; off < 1024; off <<= 1) {
        int add = (t >= off) ? sh[t - off] : 0;
        __syncthreads();
        sh[t] += add;
        __syncthreads();
    }
    if (i < n) g_incl[i] = sh[t];
    if (t == 1023) g_bsum[blockIdx.x] = sh[1023];
}

__global__ void k_scan2(int nb) {  // exclusive scan of block sums (nb <= 256)
    __shared__ int sh[256];
    int t = threadIdx.x;
    int v = (t < nb) ? g_bsum[t] : 0;
    sh[t] = v;
    __syncthreads();
    for (int off = 1; off < 256; off <<= 1) {
        int add = (t >= off) ? sh[t - off] : 0;
        __syncthreads();
        sh[t] += add;
        __syncthreads();
    }
    if (t < nb) g_bsum[t] = sh[t] - v;  // exclusive
}

__global__ void k_scan3(int n) {
    int i = blockIdx.x * blockDim.x + threadIdx.x;
    if (i >= n) return;
    int d  = g_deg[i];
    int rp = g_incl[i] - d + g_bsum[i >> 10];
    g_rowptr[i] = rp;
    g_cursor[i] = rp;
    g_dinv[i] = rsqrtf((float)d + 1.0f);
    g_cinv[i] = 1.0f / fmaxf((float)d, 1.0f);
}

__global__ void k_scatter(const void* __restrict__ ei, int e, int n) {
    int i = blockIdx.x * blockDim.x + threadIdx.x;
    if (i >= e) return;
    int is64 = g_is64;
    int s = ld_idx(ei, is64, i, n);
    int d = ld_idx(ei, is64, (long long)e + i, n);
    int pos = atomicAdd(&g_cursor[d], 1);
    float w = g_dinv[s] * g_dinv[d];
    g_edge[pos] = make_int2(s, __float_as_int(w));
}

// ---------------- GEMM: Y = act( Xa@Wa [+ Xb@Wb] [+ bias] ), all widths 64 ---
// Block: 256 threads, 128 rows. Thread tile: 4 rows x 8 cols.
template <bool DUAL, bool BIAS, bool RELU>
__global__ void k_gemm(const float* __restrict__ Xa, const float* __restrict__ Wa,
                       const float* __restrict__ Xb, const float* __restrict__ Wb,
                       const float* __restrict__ bias, float* __restrict__ Y, int n) {
    constexpr int KT = DUAL ? 128 : 64;
    constexpr int KP = KT + 4;
    extern __shared__ float sm[];
    float* Xs = sm;              // [128][KP]
    float* Ws = sm + 128 * KP;   // [KT][64]

    int tid  = threadIdx.x;
    int base = blockIdx.x * 128;

    // load weights (KT*16 float4)
    for (int i = tid; i < KT * 16; i += 256) {
        int k = i >> 4, c = (i & 15) << 2;
        const float* wsrc = (DUAL && k >= 64) ? (Wb + (size_t)(k - 64) * 64 + c)
                                              : (Wa + (size_t)k * 64 + c);
        *(float4*)&Ws[k * 64 + c] = *(const float4*)wsrc;
    }
    // load X tile (128*KT/4 float4)
    for (int i = tid; i < 128 * (KT / 4); i += 256) {
        int r  = i / (KT / 4);
        int kq = i % (KT / 4);
        int row = base + r;
        float4 v = make_float4(0.f, 0.f, 0.f, 0.f);
        if (row < n) {
            int k = kq * 4;
            const float* xsrc = (DUAL && k >= 64) ? (Xb + (size_t)row * 64 + (k - 64))
                                                  : (Xa + (size_t)row * 64 + k);
            v = *(const float4*)xsrc;
        }
        *(float4*)&Xs[r * KP + kq * 4] = v;
    }
    __syncthreads();

    int rg = tid >> 3;  // 0..31
    int cg = tid & 7;   // 0..7

    float acc[4][8];
#pragma unroll
    for (int q = 0; q < 4; q++)
#pragma unroll
        for (int c = 0; c < 8; c++) acc[q][c] = 0.f;

    for (int k = 0; k < KT; k += 4) {
        float4 xv[4];
#pragma unroll
        for (int q = 0; q < 4; q++)
            xv[q] = *(const float4*)&Xs[(rg * 4 + q) * KP + k];
#pragma unroll
        for (int j = 0; j < 4; j++) {
            float4 w0 = *(const float4*)&Ws[(k + j) * 64 + cg * 8];
            float4 w1 = *(const float4*)&Ws[(k + j) * 64 + cg * 8 + 4];
#pragma unroll
            for (int q = 0; q < 4; q++) {
                float xs = (j == 0) ? xv[q].x : (j == 1) ? xv[q].y
                         : (j == 2) ? xv[q].z : xv[q].w;
                acc[q][0] = fmaf(xs, w0.x, acc[q][0]);
                acc[q][1] = fmaf(xs, w0.y, acc[q][1]);
                acc[q][2] = fmaf(xs, w0.z, acc[q][2]);
                acc[q][3] = fmaf(xs, w0.w, acc[q][3]);
                acc[q][4] = fmaf(xs, w1.x, acc[q][4]);
                acc[q][5] = fmaf(xs, w1.y, acc[q][5]);
                acc[q][6] = fmaf(xs, w1.z, acc[q][6]);
                acc[q][7] = fmaf(xs, w1.w, acc[q][7]);
            }
        }
    }

    float4 b0 = make_float4(0.f, 0.f, 0.f, 0.f), b1 = b0;
    if (BIAS) {
        b0 = *(const float4*)&bias[cg * 8];
        b1 = *(const float4*)&bias[cg * 8 + 4];
    }
#pragma unroll
    for (int q = 0; q < 4; q++) {
        int row = base + rg * 4 + q;
        if (row >= n) continue;
        float4 o0 = make_float4(acc[q][0] + b0.x, acc[q][1] + b0.y,
                                acc[q][2] + b0.z, acc[q][3] + b0.w);
        float4 o1 = make_float4(acc[q][4] + b1.x, acc[q][5] + b1.y,
                                acc[q][6] + b1.z, acc[q][7] + b1.w);
        if (RELU) {
            o0.x = fmaxf(o0.x, 0.f); o0.y = fmaxf(o0.y, 0.f);
            o0.z = fmaxf(o0.z, 0.f); o0.w = fmaxf(o0.w, 0.f);
            o1.x = fmaxf(o1.x, 0.f); o1.y = fmaxf(o1.y, 0.f);
            o1.z = fmaxf(o1.z, 0.f); o1.w = fmaxf(o1.w, 0.f);
        }
        *(float4*)&Y[(size_t)row * 64 + cg * 8]     = o0;
        *(float4*)&Y[(size_t)row * 64 + cg * 8 + 4] = o1;
    }
}

// ---------------- aggregations (warp per node, 2 feats per lane) ------------
template <bool RELU>
__global__ void k_agg_gcn(const float* __restrict__ h, const float* __restrict__ bias,
                          float* __restrict__ out, int n) {
    int gw   = (blockIdx.x * blockDim.x + threadIdx.x) >> 5;
    int lane = threadIdx.x & 31;
    if (gw >= n) return;
    int start = g_rowptr[gw];
    int cnt   = g_deg[gw];
    float ax = 0.f, ay = 0.f;
    int2 rec = make_int2(0, 0);
    if (cnt > 0) rec = g_edge[start];
    for (int e = 0; e < cnt; e++) {
        int2 cur = rec;
        if (e + 1 < cnt) rec = g_edge[start + e + 1];
        float w  = __int_as_float(cur.y);
        float2 v = *(const float2*)(h + (size_t)cur.x * 64 + lane * 2);
        ax = fmaf(w, v.x, ax);
        ay = fmaf(w, v.y, ay);
    }
    float di = g_dinv[gw];
    float sw = di * di;
    float2 hv = *(const float2*)(h + (size_t)gw * 64 + lane * 2);
    float2 bv = *(const float2*)(bias + lane * 2);
    ax = fmaf(sw, hv.x, ax) + bv.x;
    ay = fmaf(sw, hv.y, ay) + bv.y;
    if (RELU) { ax = fmaxf(ax, 0.f); ay = fmaxf(ay, 0.f); }
    *(float2*)(out + (size_t)gw * 64 + lane * 2) = make_float2(ax, ay);
}

__global__ void k_agg_mean(const float* __restrict__ x, float* __restrict__ out, int n) {
    int gw   = (blockIdx.x * blockDim.x + threadIdx.x) >> 5;
    int lane = threadIdx.x & 31;
    if (gw >= n) return;
    int start = g_rowptr[gw];
    int cnt   = g_deg[gw];
    float ax = 0.f, ay = 0.f;
    int2 rec = make_int2(0, 0);
    if (cnt > 0) rec = g_edge[start];
    for (int e = 0; e < cnt; e++) {
        int2 cur = rec;
        if (e + 1 < cnt) rec = g_edge[start + e + 1];
        float2 v = *(const float2*)(x + (size_t)cur.x * 64 + lane * 2);
        ax += v.x;
        ay += v.y;
    }
    float ci = g_cinv[gw];
    *(float2*)(out + (size_t)gw * 64 + lane * 2) = make_float2(ax * ci, ay * ci);
}

// ---------------- LayerNorm over feature dim (warp per node, both branches) -
__global__ void k_ln(const float* __restrict__ g2, const float* __restrict__ s2,
                     const float* __restrict__ gg, const float* __restrict__ gb,
                     const float* __restrict__ sg, const float* __restrict__ sb,
                     float* __restrict__ gn, float* __restrict__ sn, int n) {
    int gw   = (blockIdx.x * blockDim.x + threadIdx.x) >> 5;
    int lane = threadIdx.x & 31;
    if (gw >= 2 * n) return;
    const float *src, *gamma, *beta;
    float* dst;
    int i;
    if (gw < n) { src = g2; gamma = gg; beta = gb; dst = gn; i = gw; }
    else        { src = s2; gamma = sg; beta = sb; dst = sn; i = gw - n; }
    float2 v = *(const float2*)(src + (size_t)i * 64 + lane * 2);
    float s = v.x + v.y;
#pragma unroll
    for (int o = 16; o > 0; o >>= 1) s += __shfl_xor_sync(0xffffffffu, s, o);
    float mu = s * (1.0f / 64.0f);
    float dx = v.x - mu, dy = v.y - mu;
    float q = dx * dx + dy * dy;
#pragma unroll
    for (int o = 16; o > 0; o >>= 1) q += __shfl_xor_sync(0xffffffffu, q, o);
    float r = rsqrtf(q * (1.0f / 64.0f) + 1e-5f);
    float2 gv = *(const float2*)(gamma + lane * 2);
    float2 bv = *(const float2*)(beta + lane * 2);
    float2 o2 = make_float2(dx * r * gv.x + bv.x, dy * r * gv.y + bv.y);
    *(float2*)(dst + (size_t)i * 64 + lane * 2) = o2;
}

// ---------------- launcher ---------------------------------------------------
extern "C" void kernel_launch(void* const* d_in, const int* in_sizes, int n_in,
                              void* d_out, int out_size) {
    const float* x        = (const float*)d_in[0];
    const void*  ei       = d_in[1];                 // int64 or int32; auto-detected
    const float* gcn_w1   = (const float*)d_in[2];
    const float* gcn_b1   = (const float*)d_in[3];
    const float* gcn_w2   = (const float*)d_in[4];
    const float* gcn_b2   = (const float*)d_in[5];
    const float* sage_wl1 = (const float*)d_in[6];
    const float* sage_bl1 = (const float*)d_in[7];
    const float* sage_wr1 = (const float*)d_in[8];
    const float* sage_wl2 = (const float*)d_in[9];
    const float* sage_bl2 = (const float*)d_in[10];
    const float* sage_wr2 = (const float*)d_in[11];
    const float* gln_g    = (const float*)d_in[12];
    const float* gln_b    = (const float*)d_in[13];
    const float* sln_g    = (const float*)d_in[14];
    const float* sln_b    = (const float*)d_in[15];
    const float* proj_w   = (const float*)d_in[16];
    const float* proj_b   = (const float*)d_in[17];
    float*       out      = (float*)d_out;

    int n = in_sizes[0] / 64;
    int e = in_sizes[1] / 2;

    float* bufbase = nullptr;
    cudaGetSymbolAddress((void**)&bufbase, g_buf);
    float* B[6];
    for (int i = 0; i < 6; i++) B[i] = bufbase + (size_t)i * N_MAX * 64;

    const size_t sm1 = (size_t)(128 * 68 + 64 * 64) * 4;    // 51200
    const size_t sm2 = (size_t)(128 * 132 + 128 * 64) * 4;  // 100352
    cudaFuncSetAttribute(k_gemm<false, false, false>,
                         cudaFuncAttributeMaxDynamicSharedMemorySize, (int)sm1);
    cudaFuncSetAttribute(k_gemm<true, true, true>,
                         cudaFuncAttributeMaxDynamicSharedMemorySize, (int)sm2);
    cudaFuncSetAttribute(k_gemm<true, true, false>,
                         cudaFuncAttributeMaxDynamicSharedMemorySize, (int)sm2);

    int nb1k = (n + 1023) / 1024;
    int gb   = (n + 127) / 128;
    int ab   = (n + 7) / 8;       // warp-per-node blocks (256 thr)
    int lb   = (2 * n + 7) / 8;

    // CSR build
    k_detect<<<1, 256>>>(ei, e, n);
    k_zero_deg<<<(n + 255) / 256, 256>>>(n);
    k_count<<<(e + 255) / 256, 256>>>(ei, e, n);
    k_scan1<<<nb1k, 1024>>>(n);
    k_scan2<<<1, 256>>>(nb1k);
    k_scan3<<<(n + 255) / 256, 256>>>(n);
    k_scatter<<<(e + 255) / 256, 256>>>(ei, e, n);

    // GCN branch
    k_gemm<false, false, false><<<gb, 256, sm1>>>(x, gcn_w1, nullptr, nullptr, nullptr, B[0], n);
    k_agg_gcn<true><<<ab, 256>>>(B[0], gcn_b1, B[1], n);
    k_gemm<false, false, false><<<gb, 256, sm1>>>(B[1], gcn_w2, nullptr, nullptr, nullptr, B[0], n);
    k_agg_gcn<false><<<ab, 256>>>(B[0], gcn_b2, B[2], n);

    // SAGE branch (mean-agg commutes with linear -> aggregate first, fused dual GEMM)
    k_agg_mean<<<ab, 256>>>(x, B[3], n);
    k_gemm<true, true, true><<<gb, 256, sm2>>>(B[3], sage_wl1, x, sage_wr1, sage_bl1, B[4], n);
    k_agg_mean<<<ab, 256>>>(B[4], B[3], n);
    k_gemm<true, true, false><<<gb, 256, sm2>>>(B[3], sage_wl2, B[4], sage_wr2, sage_bl2, B[5], n);

    // LayerNorm both branches, then fused concat-projection
    k_ln<<<lb, 256>>>(B[2], B[5], gln_g, gln_b, sln_g, sln_b, B[0], B[1], n);
    k_gemm<true, true, false><<<gb, 256, sm2>>>(B[0], proj_w, B[1], proj_w + 64 * 64, proj_b, out, n);
}

// round 8
// speedup vs baseline: 1.0275x; 1.0275x over previous
#include <cuda_runtime.h>
#include <cstdint>

#define N_MAX 100000
#define E_MAX 1250000

// ---------------- scratch (static device allocations; no runtime alloc) -----
__device__ int   g_is64;
__device__ int   g_deg[N_MAX];
__device__ int   g_incl[N_MAX];
__device__ int   g_rowptr[N_MAX];
__device__ int   g_cursor[N_MAX];
__device__ int   g_bsum[256];
__device__ float g_dinv[N_MAX];   // rsqrt(indeg+1)  (GCN)
__device__ float g_cinv[N_MAX];   // 1/max(indeg,1)  (SAGE mean)
__device__ int   g_edge[E_MAX];   // src index, bucketed by dst
__device__ float g_buf[6][(size_t)N_MAX * 64];

// ---------------- edge-index dtype detection (int64 vs int32) ---------------
__global__ void k_detect(const void* __restrict__ ei, int e, int n) {
    __shared__ int bad;
    if (threadIdx.x == 0) bad = 0;
    __syncthreads();
    const long long* p = (const long long*)ei;
    int m = e < 2048 ? e : 2048;
    for (int i = threadIdx.x; i < m; i += blockDim.x) {
        long long v = p[i];
        if (v < 0 || v >= (long long)n) bad = 1;
    }
    __syncthreads();
    if (threadIdx.x == 0) g_is64 = bad ? 0 : 1;
}

__device__ __forceinline__ int ld_idx(const void* __restrict__ ei, int is64,
                                      long long pos, int n) {
    long long v = is64 ? ((const long long*)ei)[pos]
                       : (long long)((const int*)ei)[pos];
    int s = (int)v;
    if ((unsigned)s >= (unsigned)n) s = 0;   // trap-safety clamp
    return s;
}

// ---------------- CSR build --------------------------------------------------
__global__ void k_zero_deg(int n) {
    int i = blockIdx.x * blockDim.x + threadIdx.x;
    if (i < n) g_deg[i] = 0;
}

__global__ void k_count(const void* __restrict__ ei, int e, int n) {
    int i = blockIdx.x * blockDim.x + threadIdx.x;
    if (i >= e) return;
    int is64 = g_is64;
    int d = ld_idx(ei, is64, (long long)e + i, n);
    atomicAdd(&g_deg[d], 1);
}

__global__ void k_scan1(int n) {  // per-block inclusive scan (1024/block)
    __shared__ int sh[1024];
    int t = threadIdx.x;
    int i = blockIdx.x * 1024 + t;
    int v = (i < n) ? g_deg[i] : 0;
    sh[t] = v;
    __syncthreads();
    for (int off = 1; off < 1024; off <<= 1) {
        int add = (t >= off) ? sh[t - off] : 0;
        __syncthreads();
        sh[t] += add;
        __syncthreads();
    }
    if (i < n) g_incl[i] = sh[t];
    if (t == 1023) g_bsum[blockIdx.x] = sh[1023];
}

__global__ void k_scan2(int nb) {  // exclusive scan of block sums (nb <= 256)
    __shared__ int sh[256];
    int t = threadIdx.x;
    int v = (t < nb) ? g_bsum[t] : 0;
    sh[t] = v;
    __syncthreads();
    for (int off = 1; off < 256; off <<= 1) {
        int add = (t >= off) ? sh[t - off] : 0;
        __syncthreads();
        sh[t] += add;
        __syncthreads();
    }
    if (t < nb) g_bsum[t] = sh[t] - v;  // exclusive
}

__global__ void k_scan3(int n) {
    int i = blockIdx.x * blockDim.x + threadIdx.x;
    if (i >= n) return;
    int d  = g_deg[i];
    int rp = g_incl[i] - d + g_bsum[i >> 10];
    g_rowptr[i] = rp;
    g_cursor[i] = rp;
    g_dinv[i] = rsqrtf((float)d + 1.0f);
    g_cinv[i] = 1.0f / fmaxf((float)d, 1.0f);
}

__global__ void k_scatter(const void* __restrict__ ei, int e, int n) {
    int i = blockIdx.x * blockDim.x + threadIdx.x;
    if (i >= e) return;
    int is64 = g_is64;
    int s = ld_idx(ei, is64, i, n);
    int d = ld_idx(ei, is64, (long long)e + i, n);
    int pos = atomicAdd(&g_cursor[d], 1);
    g_edge[pos] = s;
}

// ---------------- fused dual aggregations (warp per node, 2 feats/lane) -----
// Layer 1: from a single gather of x rows produce
//   outG = dinv_d * sum(dinv_s * x_s) + dinv_d^2 * x_d   (GCN pre-GEMM input)
//   outM = mean(x_s)                                      (SAGE pre-GEMM input)
__global__ void k_agg_dual1(const float* __restrict__ x,
                            float* __restrict__ outG, float* __restrict__ outM, int n) {
    int gw   = (blockIdx.x * blockDim.x + threadIdx.x) >> 5;
    int lane = threadIdx.x & 31;
    if (gw >= n) return;
    int start = g_rowptr[gw];
    int cnt   = g_deg[gw];
    float wx = 0.f, wy = 0.f, mx = 0.f, my = 0.f;
    int src = (cnt > 0) ? g_edge[start] : 0;
    for (int e = 0; e < cnt; e++) {
        int cur = src;
        if (e + 1 < cnt) src = g_edge[start + e + 1];
        float ds = g_dinv[cur];
        float2 v = *(const float2*)(x + (size_t)cur * 64 + lane * 2);
        wx = fmaf(ds, v.x, wx);
        wy = fmaf(ds, v.y, wy);
        mx += v.x;
        my += v.y;
    }
    float dd = g_dinv[gw];
    float ci = g_cinv[gw];
    float2 xv = *(const float2*)(x + (size_t)gw * 64 + lane * 2);
    float2 og = make_float2(fmaf(dd, wx, dd * dd * xv.x),
                            fmaf(dd, wy, dd * dd * xv.y));
    float2 om = make_float2(mx * ci, my * ci);
    *(float2*)(outG + (size_t)gw * 64 + lane * 2) = og;
    *(float2*)(outM + (size_t)gw * 64 + lane * 2) = om;
}

// Layer 2: one edge pass, two different feature sources.
//   outG = dinv_d * sum(dinv_s * g1_s) + dinv_d^2 * g1_d
//   outM = mean(s1_s)
__global__ void k_agg_dual2(const float* __restrict__ g1, const float* __restrict__ s1,
                            float* __restrict__ outG, float* __restrict__ outM, int n) {
    int gw   = (blockIdx.x * blockDim.x + threadIdx.x) >> 5;
    int lane = threadIdx.x & 31;
    if (gw >= n) return;
    int start = g_rowptr[gw];
    int cnt   = g_deg[gw];
    float wx = 0.f, wy = 0.f, mx = 0.f, my = 0.f;
    int src = (cnt > 0) ? g_edge[start] : 0;
    for (int e = 0; e < cnt; e++) {
        int cur = src;
        if (e + 1 < cnt) src = g_edge[start + e + 1];
        float ds = g_dinv[cur];
        float2 gv = *(const float2*)(g1 + (size_t)cur * 64 + lane * 2);
        float2 sv = *(const float2*)(s1 + (size_t)cur * 64 + lane * 2);
        wx = fmaf(ds, gv.x, wx);
        wy = fmaf(ds, gv.y, wy);
        mx += sv.x;
        my += sv.y;
    }
    float dd = g_dinv[gw];
    float ci = g_cinv[gw];
    float2 gsv = *(const float2*)(g1 + (size_t)gw * 64 + lane * 2);
    float2 og = make_float2(fmaf(dd, wx, dd * dd * gsv.x),
                            fmaf(dd, wy, dd * dd * gsv.y));
    float2 om = make_float2(mx * ci, my * ci);
    *(float2*)(outG + (size_t)gw * 64 + lane * 2) = og;
    *(float2*)(outM + (size_t)gw * 64 + lane * 2) = om;
}

// ---------------- GEMM: Y = act( Xa@Wa [+ Xb@Wb] + bias ), widths 64 --------
// Block: 256 threads, 128 rows. Thread tile: 4 rows x 8 cols.
template <bool DUAL, bool RELU>
__global__ void k_gemm(const float* __restrict__ Xa, const float* __restrict__ Wa,
                       const float* __restrict__ Xb, const float* __restrict__ Wb,
                       const float* __restrict__ bias, float* __restrict__ Y, int n) {
    constexpr int KT = DUAL ? 128 : 64;
    constexpr int KP = KT + 4;
    extern __shared__ float sm[];
    float* Xs = sm;              // [128][KP]
    float* Ws = sm + 128 * KP;   // [KT][64]

    int tid  = threadIdx.x;
    int base = blockIdx.x * 128;

    for (int i = tid; i < KT * 16; i += 256) {
        int k = i >> 4, c = (i & 15) << 2;
        const float* wsrc = (DUAL && k >= 64) ? (Wb + (size_t)(k - 64) * 64 + c)
                                              : (Wa + (size_t)k * 64 + c);
        *(float4*)&Ws[k * 64 + c] = *(const float4*)wsrc;
    }
    for (int i = tid; i < 128 * (KT / 4); i += 256) {
        int r  = i / (KT / 4);
        int kq = i % (KT / 4);
        int row = base + r;
        float4 v = make_float4(0.f, 0.f, 0.f, 0.f);
        if (row < n) {
            int k = kq * 4;
            const float* xsrc = (DUAL && k >= 64) ? (Xb + (size_t)row * 64 + (k - 64))
                                                  : (Xa + (size_t)row * 64 + k);
            v = *(const float4*)xsrc;
        }
        *(float4*)&Xs[r * KP + kq * 4] = v;
    }
    __syncthreads();

    int rg = tid >> 3;  // 0..31
    int cg = tid & 7;   // 0..7

    float acc[4][8];
#pragma unroll
    for (int q = 0; q < 4; q++)
#pragma unroll
        for (int c = 0; c < 8; c++) acc[q][c] = 0.f;

    for (int k = 0; k < KT; k += 4) {
        float4 xv[4];
#pragma unroll
        for (int q = 0; q < 4; q++)
            xv[q] = *(const float4*)&Xs[(rg * 4 + q) * KP + k];
#pragma unroll
        for (int j = 0; j < 4; j++) {
            float4 w0 = *(const float4*)&Ws[(k + j) * 64 + cg * 8];
            float4 w1 = *(const float4*)&Ws[(k + j) * 64 + cg * 8 + 4];
#pragma unroll
            for (int q = 0; q < 4; q++) {
                float xs = (j == 0) ? xv[q].x : (j == 1) ? xv[q].y
                         : (j == 2) ? xv[q].z : xv[q].w;
                acc[q][0] = fmaf(xs, w0.x, acc[q][0]);
                acc[q][1] = fmaf(xs, w0.y, acc[q][1]);
                acc[q][2] = fmaf(xs, w0.z, acc[q][2]);
                acc[q][3] = fmaf(xs, w0.w, acc[q][3]);
                acc[q][4] = fmaf(xs, w1.x, acc[q][4]);
                acc[q][5] = fmaf(xs, w1.y, acc[q][5]);
                acc[q][6] = fmaf(xs, w1.z, acc[q][6]);
                acc[q][7] = fmaf(xs, w1.w, acc[q][7]);
            }
        }
    }

    float4 b0 = *(const float4*)&bias[cg * 8];
    float4 b1 = *(const float4*)&bias[cg * 8 + 4];
#pragma unroll
    for (int q = 0; q < 4; q++) {
        int row = base + rg * 4 + q;
        if (row >= n) continue;
        float4 o0 = make_float4(acc[q][0] + b0.x, acc[q][1] + b0.y,
                                acc[q][2] + b0.z, acc[q][3] + b0.w);
        float4 o1 = make_float4(acc[q][4] + b1.x, acc[q][5] + b1.y,
                                acc[q][6] + b1.z, acc[q][7] + b1.w);
        if (RELU) {
            o0.x = fmaxf(o0.x, 0.f); o0.y = fmaxf(o0.y, 0.f);
            o0.z = fmaxf(o0.z, 0.f); o0.w = fmaxf(o0.w, 0.f);
            o1.x = fmaxf(o1.x, 0.f); o1.y = fmaxf(o1.y, 0.f);
            o1.z = fmaxf(o1.z, 0.f); o1.w = fmaxf(o1.w, 0.f);
        }
        *(float4*)&Y[(size_t)row * 64 + cg * 8]     = o0;
        *(float4*)&Y[(size_t)row * 64 + cg * 8 + 4] = o1;
    }
}

// ---------------- projection GEMM with fused per-branch LayerNorm -----------
// out = [LN(g2)|LN(s2)] @ W(128x64) + bias.  LN applied in the shared tile.
__global__ void k_proj(const float* __restrict__ G, const float* __restrict__ S,
                       const float* __restrict__ gg, const float* __restrict__ gb,
                       const float* __restrict__ sg, const float* __restrict__ sb,
                       const float* __restrict__ W, const float* __restrict__ bias,
                       float* __restrict__ Y, int n) {
    constexpr int KT = 128, KP = 132;
    extern __shared__ float sm[];
    float* Xs  = sm;                       // [128][132]
    float* Ws  = sm + 128 * KP;            // [128][64]
    float* gam = Ws + 128 * 64;            // [128]
    float* bet = gam + 128;                // [128]

    int tid  = threadIdx.x;
    int base = blockIdx.x * 128;

    if (tid < 128) {
        gam[tid] = (tid < 64) ? gg[tid] : sg[tid - 64];
        bet[tid] = (tid < 64) ? gb[tid] : sb[tid - 64];
    }
    for (int i = tid; i < 128 * 16; i += 256) {
        int k = i >> 4, c = (i & 15) << 2;
        *(float4*)&Ws[k * 64 + c] = *(const float4*)(W + (size_t)k * 64 + c);
    }
    for (int i = tid; i < 128 * 32; i += 256) {
        int r  = i >> 5;
        int kq = i & 31;
        int row = base + r;
        float4 v = make_float4(0.f, 0.f, 0.f, 0.f);
        if (row < n) {
            int k = kq * 4;
            const float* xsrc = (k >= 64) ? (S + (size_t)row * 64 + (k - 64))
                                          : (G + (size_t)row * 64 + k);
            v = *(const float4*)xsrc;
        }
        *(float4*)&Xs[r * KP + kq * 4] = v;
    }
    __syncthreads();

    // LayerNorm in place: thread -> (row = tid/2, half = tid&1), 64 values each
    {
        int r    = tid >> 1;
        int half = tid & 1;
        float* p = &Xs[r * KP + half * 64];
        float s = 0.f, q = 0.f;
#pragma unroll
        for (int c = 0; c < 64; c += 4) {
            float4 v = *(float4*)&p[c];
            s += v.x + v.y + v.z + v.w;
            q += v.x * v.x + v.y * v.y + v.z * v.z + v.w * v.w;
        }
        float mu  = s * (1.0f / 64.0f);
        float var = fmaxf(q * (1.0f / 64.0f) - mu * mu, 0.f);
        float rs  = rsqrtf(var + 1e-5f);
        const float* gm = &gam[half * 64];
        const float* bt = &bet[half * 64];
#pragma unroll
        for (int c = 0; c < 64; c += 4) {
            float4 v = *(float4*)&p[c];
            v.x = (v.x - mu) * rs * gm[c]     + bt[c];
            v.y = (v.y - mu) * rs * gm[c + 1] + bt[c + 1];
            v.z = (v.z - mu) * rs * gm[c + 2] + bt[c + 2];
            v.w = (v.w - mu) * rs * gm[c + 3] + bt[c + 3];
            *(float4*)&p[c] = v;
        }
    }
    __syncthreads();

    int rg = tid >> 3;
    int cg = tid & 7;

    float acc[4][8];
#pragma unroll
    for (int q = 0; q < 4; q++)
#pragma unroll
        for (int c = 0; c < 8; c++) acc[q][c] = 0.f;

    for (int k = 0; k < KT; k += 4) {
        float4 xv[4];
#pragma unroll
        for (int q = 0; q < 4; q++)
            xv[q] = *(const float4*)&Xs[(rg * 4 + q) * KP + k];
#pragma unroll
        for (int j = 0; j < 4; j++) {
            float4 w0 = *(const float4*)&Ws[(k + j) * 64 + cg * 8];
            float4 w1 = *(const float4*)&Ws[(k + j) * 64 + cg * 8 + 4];
#pragma unroll
            for (int q = 0; q < 4; q++) {
                float xs = (j == 0) ? xv[q].x : (j == 1) ? xv[q].y
                         : (j == 2) ? xv[q].z : xv[q].w;
                acc[q][0] = fmaf(xs, w0.x, acc[q][0]);
                acc[q][1] = fmaf(xs, w0.y, acc[q][1]);
                acc[q][2] = fmaf(xs, w0.z, acc[q][2]);
                acc[q][3] = fmaf(xs, w0.w, acc[q][3]);
                acc[q][4] = fmaf(xs, w1.x, acc[q][4]);
                acc[q][5] = fmaf(xs, w1.y, acc[q][5]);
                acc[q][6] = fmaf(xs, w1.z, acc[q][6]);
                acc[q][7] = fmaf(xs, w1.w, acc[q][7]);
            }
        }
    }

    float4 b0 = *(const float4*)&bias[cg * 8];
    float4 b1 = *(const float4*)&bias[cg * 8 + 4];
#pragma unroll
    for (int q = 0; q < 4; q++) {
        int row = base + rg * 4 + q;
        if (row >= n) continue;
        float4 o0 = make_float4(acc[q][0] + b0.x, acc[q][1] + b0.y,
                                acc[q][2] + b0.z, acc[q][3] + b0.w);
        float4 o1 = make_float4(acc[q][4] + b1.x, acc[q][5] + b1.y,
                                acc[q][6] + b1.z, acc[q][7] + b1.w);
        *(float4*)&Y[(size_t)row * 64 + cg * 8]     = o0;
        *(float4*)&Y[(size_t)row * 64 + cg * 8 + 4] = o1;
    }
}

// ---------------- launcher ---------------------------------------------------
extern "C" void kernel_launch(void* const* d_in, const int* in_sizes, int n_in,
                              void* d_out, int out_size) {
    const float* x        = (const float*)d_in[0];
    const void*  ei       = d_in[1];                 // int64 or int32; auto-detected
    const float* gcn_w1   = (const float*)d_in[2];
    const float* gcn_b1   = (const float*)d_in[3];
    const float* gcn_w2   = (const float*)d_in[4];
    const float* gcn_b2   = (const float*)d_in[5];
    const float* sage_wl1 = (const float*)d_in[6];
    const float* sage_bl1 = (const float*)d_in[7];
    const float* sage_wr1 = (const float*)d_in[8];
    const float* sage_wl2 = (const float*)d_in[9];
    const float* sage_bl2 = (const float*)d_in[10];
    const float* sage_wr2 = (const float*)d_in[11];
    const float* gln_g    = (const float*)d_in[12];
    const float* gln_b    = (const float*)d_in[13];
    const float* sln_g    = (const float*)d_in[14];
    const float* sln_b    = (const float*)d_in[15];
    const float* proj_w   = (const float*)d_in[16];
    const float* proj_b   = (const float*)d_in[17];
    float*       out      = (float*)d_out;

    int n = in_sizes[0] / 64;
    int e = in_sizes[1] / 2;

    float* bufbase = nullptr;
    cudaGetSymbolAddress((void**)&bufbase, g_buf);
    float* B[6];
    for (int i = 0; i < 6; i++) B[i] = bufbase + (size_t)i * N_MAX * 64;

    const size_t sm1 = (size_t)(128 * 68 + 64 * 64) * 4;           // 51200
    const size_t sm2 = (size_t)(128 * 132 + 128 * 64) * 4;         // 100352
    const size_t smp = (size_t)(128 * 132 + 128 * 64 + 256) * 4;   // 101376
    cudaFuncSetAttribute(k_gemm<false, true>,
                         cudaFuncAttributeMaxDynamicSharedMemorySize, (int)sm1);
    cudaFuncSetAttribute(k_gemm<false, false>,
                         cudaFuncAttributeMaxDynamicSharedMemorySize, (int)sm1);
    cudaFuncSetAttribute(k_gemm<true, true>,
                         cudaFuncAttributeMaxDynamicSharedMemorySize, (int)sm2);
    cudaFuncSetAttribute(k_gemm<true, false>,
                         cudaFuncAttributeMaxDynamicSharedMemorySize, (int)sm2);
    cudaFuncSetAttribute(k_proj,
                         cudaFuncAttributeMaxDynamicSharedMemorySize, (int)smp);

    int nb1k = (n + 1023) / 1024;
    int gb   = (n + 127) / 128;
    int ab   = (n + 7) / 8;       // warp-per-node blocks (256 thr)

    // CSR build
    k_detect<<<1, 256>>>(ei, e, n);
    k_zero_deg<<<(n + 255) / 256, 256>>>(n);
    k_count<<<(e + 255) / 256, 256>>>(ei, e, n);
    k_scan1<<<nb1k, 1024>>>(n);
    k_scan2<<<1, 256>>>(nb1k);
    k_scan3<<<(n + 255) / 256, 256>>>(n);
    k_scatter<<<(e + 255) / 256, 256>>>(ei, e, n);

    // Layer 1: fused dual aggregation over x, then the two layer-1 GEMMs
    k_agg_dual1<<<ab, 256>>>(x, B[0], B[1], n);                       // B0=GCN-agg(x), B1=mean(x)
    k_gemm<false, true><<<gb, 256, sm1>>>(B[0], gcn_w1, nullptr, nullptr, gcn_b1, B[2], n);  // g1
    k_gemm<true,  true><<<gb, 256, sm2>>>(B[1], sage_wl1, x, sage_wr1, sage_bl1, B[3], n);   // s1

    // Layer 2: fused dual aggregation over (g1, s1), then the two layer-2 GEMMs
    k_agg_dual2<<<ab, 256>>>(B[2], B[3], B[0], B[1], n);              // B0=GCN-agg(g1), B1=mean(s1)
    k_gemm<false, false><<<gb, 256, sm1>>>(B[0], gcn_w2, nullptr, nullptr, gcn_b2, B[4], n); // g2
    k_gemm<true,  false><<<gb, 256, sm2>>>(B[1], sage_wl2, B[3], sage_wr2, sage_bl2, B[5], n); // s2

    // Fused LayerNorm + concat projection
    k_proj<<<gb, 256, smp>>>(B[4], B[5], gln_g, gln_b, sln_g, sln_b,
                             proj_w, proj_b, out, n);
}